// round 1
// baseline (speedup 1.0000x reference)
#include <cuda_runtime.h>

#define NN 100000
#define NE 1000000
#define KF 128
#define HID 64

// ---------------- scratch (static device globals; no allocs allowed) ----------------
__device__ float g_H0[NN * HID];
__device__ float g_H1[NN * HID];
__device__ float g_H2[NN * HID];
__device__ float g_sa0[NN];
__device__ float g_sb0[NN];
__device__ float g_sb1[NN];
__device__ float g_sb2[NN];
__device__ int   g_deg[NN];
__device__ int   g_cursor[NN];
__device__ int   g_offs[NN];
__device__ int   g_part[128];
__device__ float g_score[NE];
__device__ int   g_e1s[NE];
__device__ int   g_e2s[NE];

// ---------------- packed f32x2 helpers (Blackwell 2x fp32 pipe) ----------------
__device__ __forceinline__ unsigned long long pk2(float x, float y) {
    unsigned long long r;
    asm("mov.b64 %0, {%1, %2};" : "=l"(r) : "f"(x), "f"(y));
    return r;
}
__device__ __forceinline__ unsigned long long ffma2(unsigned long long a,
                                                    unsigned long long b,
                                                    unsigned long long c) {
    unsigned long long d;
    asm("fma.rn.f32x2 %0, %1, %2, %3;" : "=l"(d) : "l"(a), "l"(b), "l"(c));
    return d;
}
__device__ __forceinline__ float2 upk2(unsigned long long v) {
    float2 r;
    asm("mov.b64 {%0, %1}, %2;" : "=f"(r.x), "=f"(r.y) : "l"(v));
    return r;
}

// ---------------- kernel 0: zero histogram state ----------------
__global__ void zero_hist_kernel() {
    int i = blockIdx.x * blockDim.x + threadIdx.x;
    if (i < NN) { g_deg[i] = 0; g_cursor[i] = 0; }
}

// ---------------- kernel 1: H_k = feat_k @ W + b  (f32x2 register-tiled GEMM) ----------------
// Block tile: 256 rows x 64 cols, BK = 32. Thread tile: 8 rows x 8 cols.
__global__ __launch_bounds__(256) void gemm_kernel(
    const float* __restrict__ f0, const float* __restrict__ f1,
    const float* __restrict__ f2, const float* __restrict__ W,
    const float* __restrict__ b)
{
    __shared__ float As[256 * 32];   // [row][k] with k4-swizzle by (row>>3)&7
    __shared__ float Ws[32 * 64];    // [k][c]

    int fk = blockIdx.y;
    const float* feat = (fk == 0) ? f0 : ((fk == 1) ? f1 : f2);
    float* H = (fk == 0) ? g_H0 : ((fk == 1) ? g_H1 : g_H2);

    int row0 = blockIdx.x * 256;
    int tid = threadIdx.x;
    int tx = tid & 7;        // 8 col-groups
    int ty = tid >> 3;       // 32 row-groups (8 rows each)

    unsigned long long acc[8][4];
#pragma unroll
    for (int i = 0; i < 8; i++)
#pragma unroll
        for (int j = 0; j < 4; j++) acc[i][j] = 0ull;

    for (int kc = 0; kc < KF; kc += 32) {
        // load A chunk (256 rows x 32 floats), swizzled float4 stores (conflict-free)
#pragma unroll
        for (int it = 0; it < 8; it++) {
            int f4 = tid + it * 256;         // 0..2047
            int row = f4 >> 3;
            int k4 = f4 & 7;
            int gr = row0 + row;
            float4 v = make_float4(0.f, 0.f, 0.f, 0.f);
            if (gr < NN)
                v = *reinterpret_cast<const float4*>(&feat[gr * KF + kc + k4 * 4]);
            reinterpret_cast<float4*>(As)[row * 8 + (k4 ^ ((row >> 3) & 7))] = v;
        }
        // load W chunk (32 x 64), linear float4 copy
#pragma unroll
        for (int q = 0; q < 2; q++) {
            int f4 = tid * 2 + q;            // 0..511
            reinterpret_cast<float4*>(Ws)[f4] =
                reinterpret_cast<const float4*>(&W[kc * 64])[f4];
        }
        __syncthreads();

#pragma unroll
        for (int k = 0; k < 32; k += 4) {
            float4 av[8];
#pragma unroll
            for (int i = 0; i < 8; i++) {
                int row = ty * 8 + i;
                av[i] = reinterpret_cast<float4*>(As)[row * 8 + ((k >> 2) ^ (ty & 7))];
            }
#pragma unroll
            for (int kp = 0; kp < 4; kp++) {
                float4 wA = reinterpret_cast<float4*>(Ws)[(k + kp) * 16 + tx];
                float4 wB = reinterpret_cast<float4*>(Ws)[(k + kp) * 16 + 8 + tx];
                unsigned long long w0 = pk2(wA.x, wA.y), w1 = pk2(wA.z, wA.w);
                unsigned long long w2 = pk2(wB.x, wB.y), w3 = pk2(wB.z, wB.w);
#pragma unroll
                for (int i = 0; i < 8; i++) {
                    float a = (kp == 0) ? av[i].x : (kp == 1) ? av[i].y
                             : (kp == 2) ? av[i].z : av[i].w;
                    unsigned long long aa = pk2(a, a);
                    acc[i][0] = ffma2(aa, w0, acc[i][0]);
                    acc[i][1] = ffma2(aa, w1, acc[i][1]);
                    acc[i][2] = ffma2(aa, w2, acc[i][2]);
                    acc[i][3] = ffma2(aa, w3, acc[i][3]);
                }
            }
        }
        __syncthreads();
    }

    float4 b0 = *reinterpret_cast<const float4*>(&b[tx * 4]);
    float4 b1 = *reinterpret_cast<const float4*>(&b[32 + tx * 4]);
#pragma unroll
    for (int i = 0; i < 8; i++) {
        int gr = row0 + ty * 8 + i;
        if (gr < NN) {
            float2 p0 = upk2(acc[i][0]), p1 = upk2(acc[i][1]);
            float2 p2 = upk2(acc[i][2]), p3 = upk2(acc[i][3]);
            float4 o0 = make_float4(p0.x + b0.x, p0.y + b0.y, p1.x + b0.z, p1.y + b0.w);
            float4 o1 = make_float4(p2.x + b1.x, p2.y + b1.y, p3.x + b1.z, p3.y + b1.w);
            *reinterpret_cast<float4*>(&H[gr * HID + tx * 4]) = o0;
            *reinterpret_cast<float4*>(&H[gr * HID + 32 + tx * 4]) = o1;
        }
    }
}

// ---------------- kernel 2: per-node attention scalar projections ----------------
__global__ void proj_kernel(const float* __restrict__ Wa) {
    int g = blockIdx.x * blockDim.x + threadIdx.x;
    int gw = g >> 5;
    int lane = g & 31;
    if (gw >= 3 * NN) return;
    int kk = gw / NN;
    int r = gw - kk * NN;
    const float* H = (kk == 0) ? g_H0 : ((kk == 1) ? g_H1 : g_H2);
    float h0 = H[r * HID + lane];
    float h1 = H[r * HID + 32 + lane];
    float pa = h0 * Wa[lane] + h1 * Wa[32 + lane];
    float pb = h0 * Wa[64 + lane] + h1 * Wa[96 + lane];
#pragma unroll
    for (int off = 16; off; off >>= 1) {
        pa += __shfl_xor_sync(0xffffffffu, pa, off);
        pb += __shfl_xor_sync(0xffffffffu, pb, off);
    }
    if (lane == 0) {
        if (kk == 0) { g_sa0[r] = pa; g_sb0[r] = pb; }
        else if (kk == 1) g_sb1[r] = pb;
        else g_sb2[r] = pb;
    }
}

// ---------------- kernel 3: degree histogram ----------------
__global__ void hist_kernel(const int* __restrict__ e0) {
    for (int i = blockIdx.x * blockDim.x + threadIdx.x; i < NE;
         i += gridDim.x * blockDim.x)
        atomicAdd(&g_deg[e0[i]], 1);
}

// ---------------- kernels 4a/4b/4c: exclusive scan of degrees ----------------
__global__ void scan1_kernel() {
    __shared__ int s[1024];
    int i = blockIdx.x * 1024 + threadIdx.x;
    int v = (i < NN) ? g_deg[i] : 0;
    s[threadIdx.x] = v;
    __syncthreads();
    for (int off = 1; off < 1024; off <<= 1) {
        int t = (threadIdx.x >= (unsigned)off) ? s[threadIdx.x - off] : 0;
        __syncthreads();
        s[threadIdx.x] += t;
        __syncthreads();
    }
    if (i < NN) g_offs[i] = s[threadIdx.x] - v;   // exclusive
    if (threadIdx.x == 1023) g_part[blockIdx.x] = s[1023];
}
__global__ void scan2_kernel(int nb) {
    if (threadIdx.x == 0) {
        int run = 0;
        for (int b = 0; b < nb; b++) { int t = g_part[b]; g_part[b] = run; run += t; }
    }
}
__global__ void scan3_kernel() {
    int i = blockIdx.x * 1024 + threadIdx.x;
    if (i < NN) g_offs[i] += g_part[blockIdx.x];
}

// ---------------- kernel 5: scatter edges into CSR order + compute scores ----------------
__global__ void scatter_kernel(const int* __restrict__ e0, const int* __restrict__ e1,
                               const int* __restrict__ e2, const float* __restrict__ b_att) {
    float ba = b_att[0];
    for (int e = blockIdx.x * blockDim.x + threadIdx.x; e < NE;
         e += gridDim.x * blockDim.x) {
        int n = e0[e], i1 = e1[e], i2 = e2[e];
        float sc = tanhf(g_sa0[n] +
                         (g_sb0[n] + g_sb1[i1] + g_sb2[i2]) * (1.0f / 3.0f) + ba);
        int p = g_offs[n] + atomicAdd(&g_cursor[n], 1);
        g_score[p] = sc;
        g_e1s[p] = i1;
        g_e2s[p] = i2;
    }
}

// ---------------- kernel 6: per-node softmax + weighted aggregation (no atomics) ----------------
__global__ __launch_bounds__(256) void agg_kernel(const float* __restrict__ bias,
                                                  float* __restrict__ out) {
    int gw = (blockIdx.x * 256 + threadIdx.x) >> 5;
    int lane = threadIdx.x & 31;
    if (gw >= NN) return;
    int n = gw;
    int d = g_deg[n];
    int start = g_offs[n];
    float bz0 = bias[lane], bz1 = bias[32 + lane];
    if (d == 0) {
        out[n * HID + lane] = bz0;
        out[n * HID + 32 + lane] = bz1;
        return;
    }
    // segment max
    float m = -1e30f;
    for (int j = lane; j < d; j += 32) m = fmaxf(m, g_score[start + j]);
#pragma unroll
    for (int off = 16; off; off >>= 1)
        m = fmaxf(m, __shfl_xor_sync(0xffffffffu, m, off));
    // fused exp-sum + weighted aggregation (normalize at the end)
    float acc0 = 0.f, acc1 = 0.f, sumex = 0.f;
    for (int j = 0; j < d; j++) {
        float sc = g_score[start + j];
        int i1 = g_e1s[start + j];
        int i2 = g_e2s[start + j];
        float ex = __expf(sc - m);
        sumex += ex;
        acc0 += ex * (g_H1[i1 * HID + lane] + g_H2[i2 * HID + lane]);
        acc1 += ex * (g_H1[i1 * HID + 32 + lane] + g_H2[i2 * HID + 32 + lane]);
    }
    float inv = 1.0f / sumex;
    out[n * HID + lane] =
        (g_H0[n * HID + lane] + acc0 * inv) * (1.0f / 3.0f) + bz0;
    out[n * HID + 32 + lane] =
        (g_H0[n * HID + 32 + lane] + acc1 * inv) * (1.0f / 3.0f) + bz1;
}

// ---------------- launch ----------------
extern "C" void kernel_launch(void* const* d_in, const int* in_sizes, int n_in,
                              void* d_out, int out_size) {
    const float* feats[3] = {0, 0, 0};
    const int* edges[3] = {0, 0, 0};
    const float *W_feat = 0, *b_feat = 0, *W_att = 0, *b_att = 0, *bias = 0;
    int nf = 0, ne = 0;
    for (int i = 0; i < n_in; i++) {
        int s = in_sizes[i];
        if (s == NN * KF) { if (nf < 3) feats[nf++] = (const float*)d_in[i]; }
        else if (s == NE) { if (ne < 3) edges[ne++] = (const int*)d_in[i]; }
        else if (s == KF * HID) W_feat = (const float*)d_in[i];
        else if (s == 2 * HID) W_att = (const float*)d_in[i];
        else if (s == HID) { if (!b_feat) b_feat = (const float*)d_in[i]; else bias = (const float*)d_in[i]; }
        else if (s == 1) b_att = (const float*)d_in[i];
    }
    float* out = (float*)d_out;

    zero_hist_kernel<<<(NN + 255) / 256, 256>>>();
    gemm_kernel<<<dim3((NN + 255) / 256, 3), 256>>>(feats[0], feats[1], feats[2],
                                                    W_feat, b_feat);
    proj_kernel<<<(3 * NN * 32 + 255) / 256, 256>>>(W_att);
    hist_kernel<<<2048, 256>>>(edges[0]);
    scan1_kernel<<<(NN + 1023) / 1024, 1024>>>();
    scan2_kernel<<<1, 32>>>((NN + 1023) / 1024);
    scan3_kernel<<<(NN + 1023) / 1024, 1024>>>();
    scatter_kernel<<<2048, 256>>>(edges[0], edges[1], edges[2], b_att);
    agg_kernel<<<(NN + 7) / 8, 256>>>(bias, out);
}

// round 2
// speedup vs baseline: 1.7574x; 1.7574x over previous
#include <cuda_runtime.h>

#define NN 100000
#define NE 1000000
#define KF 128
#define HID 64

// ---------------- scratch ----------------
__device__ float g_H0[NN * HID];
__device__ float g_H1[NN * HID];
__device__ float g_H2[NN * HID];
__device__ float g_s00[NN];          // H0.Wa_top + H0.Wa_bot/3 + b_att
__device__ float g_sb1[NN];          // H1.Wa_bot/3
__device__ float g_sb2[NN];          // H2.Wa_bot/3
__device__ int   g_deg[NN];
__device__ int   g_cursor[NN];
__device__ int   g_offs[NN];
__device__ int   g_part[128];
__device__ float4 g_pack[NE];        // {ex, i1, i2, pad}

// ---------------- f32x2 + misc helpers ----------------
__device__ __forceinline__ unsigned long long pk2(float x, float y) {
    unsigned long long r;
    asm("mov.b64 %0, {%1, %2};" : "=l"(r) : "f"(x), "f"(y));
    return r;
}
__device__ __forceinline__ unsigned long long ffma2(unsigned long long a,
                                                    unsigned long long b,
                                                    unsigned long long c) {
    unsigned long long d;
    asm("fma.rn.f32x2 %0, %1, %2, %3;" : "=l"(d) : "l"(a), "l"(b), "l"(c));
    return d;
}
__device__ __forceinline__ float2 upk2(unsigned long long v) {
    float2 r;
    asm("mov.b64 {%0, %1}, %2;" : "=f"(r.x), "=f"(r.y) : "l"(v));
    return r;
}
__device__ __forceinline__ float dot4(float4 a, float4 b) {
    return a.x * b.x + a.y * b.y + a.z * b.z + a.w * b.w;
}
__device__ __forceinline__ void cpa16(void* smem, const void* gmem) {
    unsigned s = (unsigned)__cvta_generic_to_shared(smem);
    asm volatile("cp.async.ca.shared.global [%0], [%1], 16;\n" :: "r"(s), "l"(gmem));
}

// ---------------- kernel 0: zero counters ----------------
__global__ void zero_kernel() {
    int i = blockIdx.x * blockDim.x + threadIdx.x;
    if (i < NN) { g_deg[i] = 0; g_cursor[i] = 0; }
}

// ---------------- kernel 1: H_k = feat_k @ W + b (cp.async double-buffered,
//                   f32x2 math, fused attention-scalar epilogue) ----------------
// Block tile 256x64, BK=16, thread tile 8x8.
__global__ __launch_bounds__(256) void gemm_kernel(
    const float* __restrict__ f0, const float* __restrict__ f1,
    const float* __restrict__ f2, const float* __restrict__ W,
    const float* __restrict__ b, const float* __restrict__ Wa,
    const float* __restrict__ b_att)
{
    __shared__ float As[2][256 * 16];   // 16KB x2, swizzled
    __shared__ float Ws[2][16 * 64];    //  4KB x2

    int fk = blockIdx.y;
    const float* feat = (fk == 0) ? f0 : ((fk == 1) ? f1 : f2);
    float* H = (fk == 0) ? g_H0 : ((fk == 1) ? g_H1 : g_H2);

    int row0 = blockIdx.x * 256;
    int tid = threadIdx.x;
    int tx = tid & 7;
    int ty = tid >> 3;

    // src row for this thread's A copies (clamped for tail block)
    int arow = row0 + tid;
    if (arow >= NN) arow = NN - 1;
    const float* asrc = feat + (long long)arow * KF;

    unsigned long long acc[8][4];
#pragma unroll
    for (int i = 0; i < 8; i++)
#pragma unroll
        for (int j = 0; j < 4; j++) acc[i][j] = 0ull;

    // issue chunk c into buffer bsel
    auto issue = [&](int c, int bsel) {
        int kc = c * 16;
#pragma unroll
        for (int k4 = 0; k4 < 4; k4++) {
            float* dst = &As[bsel][(tid * 4 + (k4 ^ ((tid >> 3) & 3))) * 4];
            cpa16(dst, asrc + kc + k4 * 4);
        }
        cpa16(&Ws[bsel][tid * 4], W + kc * 64 + tid * 4);
    };

    issue(0, 0);
    asm volatile("cp.async.commit_group;\n");

    for (int c = 0; c < 8; c++) {
        if (c + 1 < 8) {
            issue(c + 1, (c + 1) & 1);
            asm volatile("cp.async.commit_group;\n");
            asm volatile("cp.async.wait_group 1;\n");
        } else {
            asm volatile("cp.async.wait_group 0;\n");
        }
        __syncthreads();

        const float4* As4 = reinterpret_cast<const float4*>(As[c & 1]);
        const float4* Ws4 = reinterpret_cast<const float4*>(Ws[c & 1]);
#pragma unroll
        for (int kg = 0; kg < 4; kg++) {
            float4 av[8];
#pragma unroll
            for (int i = 0; i < 8; i++) {
                int row = ty * 8 + i;
                av[i] = As4[row * 4 + (kg ^ ((row >> 3) & 3))];
            }
#pragma unroll
            for (int kp = 0; kp < 4; kp++) {
                float4 wA = Ws4[(kg * 4 + kp) * 16 + tx];
                float4 wB = Ws4[(kg * 4 + kp) * 16 + 8 + tx];
                unsigned long long w0 = pk2(wA.x, wA.y), w1 = pk2(wA.z, wA.w);
                unsigned long long w2 = pk2(wB.x, wB.y), w3 = pk2(wB.z, wB.w);
#pragma unroll
                for (int i = 0; i < 8; i++) {
                    float a = (kp == 0) ? av[i].x : (kp == 1) ? av[i].y
                             : (kp == 2) ? av[i].z : av[i].w;
                    unsigned long long aa = pk2(a, a);
                    acc[i][0] = ffma2(aa, w0, acc[i][0]);
                    acc[i][1] = ffma2(aa, w1, acc[i][1]);
                    acc[i][2] = ffma2(aa, w2, acc[i][2]);
                    acc[i][3] = ffma2(aa, w3, acc[i][3]);
                }
            }
        }
        __syncthreads();
    }

    // epilogue: bias add, store H, fused attention scalar projections
    float4 b0 = *reinterpret_cast<const float4*>(&b[tx * 4]);
    float4 b1 = *reinterpret_cast<const float4*>(&b[32 + tx * 4]);
    float4 wt0 = *reinterpret_cast<const float4*>(&Wa[tx * 4]);
    float4 wt1 = *reinterpret_cast<const float4*>(&Wa[32 + tx * 4]);
    float4 wb0 = *reinterpret_cast<const float4*>(&Wa[64 + tx * 4]);
    float4 wb1 = *reinterpret_cast<const float4*>(&Wa[96 + tx * 4]);
    float ba = (fk == 0) ? __ldg(b_att) : 0.f;

#pragma unroll
    for (int i = 0; i < 8; i++) {
        int gr = row0 + ty * 8 + i;
        float2 p0 = upk2(acc[i][0]), p1 = upk2(acc[i][1]);
        float2 p2 = upk2(acc[i][2]), p3 = upk2(acc[i][3]);
        float4 o0 = make_float4(p0.x + b0.x, p0.y + b0.y, p1.x + b0.z, p1.y + b0.w);
        float4 o1 = make_float4(p2.x + b1.x, p2.y + b1.y, p3.x + b1.z, p3.y + b1.w);
        if (gr < NN) {
            *reinterpret_cast<float4*>(&H[gr * HID + tx * 4]) = o0;
            *reinterpret_cast<float4*>(&H[gr * HID + 32 + tx * 4]) = o1;
        }
        float pa = dot4(o0, wt0) + dot4(o1, wt1);
        float pb = dot4(o0, wb0) + dot4(o1, wb1);
#pragma unroll
        for (int off = 1; off < 8; off <<= 1) {
            pa += __shfl_xor_sync(0xffffffffu, pa, off);
            pb += __shfl_xor_sync(0xffffffffu, pb, off);
        }
        if (tx == 0 && gr < NN) {
            if (fk == 0)      g_s00[gr] = pa + pb * (1.0f / 3.0f) + ba;
            else if (fk == 1) g_sb1[gr] = pb * (1.0f / 3.0f);
            else              g_sb2[gr] = pb * (1.0f / 3.0f);
        }
    }
}

// ---------------- kernel 2: degree histogram (int4 vectorized) ----------------
__global__ void hist_kernel(const int* __restrict__ e0) {
    int i = blockIdx.x * blockDim.x + threadIdx.x;
    if (i < NE / 4) {
        int4 v = reinterpret_cast<const int4*>(e0)[i];
        atomicAdd(&g_deg[v.x], 1);
        atomicAdd(&g_deg[v.y], 1);
        atomicAdd(&g_deg[v.z], 1);
        atomicAdd(&g_deg[v.w], 1);
    }
}

// ---------------- kernels 3a/3b/3c: exclusive scan ----------------
__global__ void scan1_kernel() {
    __shared__ int s[1024];
    int i = blockIdx.x * 1024 + threadIdx.x;
    int v = (i < NN) ? g_deg[i] : 0;
    s[threadIdx.x] = v;
    __syncthreads();
    for (int off = 1; off < 1024; off <<= 1) {
        int t = (threadIdx.x >= (unsigned)off) ? s[threadIdx.x - off] : 0;
        __syncthreads();
        s[threadIdx.x] += t;
        __syncthreads();
    }
    if (i < NN) g_offs[i] = s[threadIdx.x] - v;
    if (threadIdx.x == 1023) g_part[blockIdx.x] = s[1023];
}
__global__ void scan2_kernel(int nb) {
    if (threadIdx.x == 0) {
        int run = 0;
        for (int b = 0; b < nb; b++) { int t = g_part[b]; g_part[b] = run; run += t; }
    }
}
__global__ void scan3_kernel() {
    int i = blockIdx.x * 1024 + threadIdx.x;
    if (i < NN) g_offs[i] += g_part[blockIdx.x];
}

// ---------------- kernel 4: edge pass — exp(tanh(score)), packed CSR scatter ----------------
__global__ void edge_kernel(const int* __restrict__ e0, const int* __restrict__ e1,
                            const int* __restrict__ e2) {
    int i = blockIdx.x * blockDim.x + threadIdx.x;
    if (i >= NE / 4) return;
    int4 a = reinterpret_cast<const int4*>(e0)[i];
    int4 b = reinterpret_cast<const int4*>(e1)[i];
    int4 c = reinterpret_cast<const int4*>(e2)[i];
#pragma unroll
    for (int q = 0; q < 4; q++) {
        int n  = (q == 0) ? a.x : (q == 1) ? a.y : (q == 2) ? a.z : a.w;
        int i1 = (q == 0) ? b.x : (q == 1) ? b.y : (q == 2) ? b.z : b.w;
        int i2 = (q == 0) ? c.x : (q == 1) ? c.y : (q == 2) ? c.z : c.w;
        float sc = tanhf(g_s00[n] + g_sb1[i1] + g_sb2[i2]);
        float ex = __expf(sc);   // sc in [-1,1]: no overflow; max-shift unnecessary
        int p = g_offs[n] + atomicAdd(&g_cursor[n], 1);
        g_pack[p] = make_float4(ex, __int_as_float(i1), __int_as_float(i2), 0.f);
    }
}

// ---------------- kernel 5: per-node softmax-normalize + aggregate ----------------
__global__ __launch_bounds__(256) void agg_kernel(const float* __restrict__ bias,
                                                  float* __restrict__ out) {
    int gw = (blockIdx.x * 256 + threadIdx.x) >> 5;
    int lane = threadIdx.x & 31;
    if (gw >= NN) return;
    int d = g_deg[gw];
    int start = g_offs[gw];
    float2 bz = *reinterpret_cast<const float2*>(&bias[2 * lane]);
    float2 o;
    if (d == 0) {
        o = bz;
    } else {
        float2 acc = make_float2(0.f, 0.f);
        float sumex = 0.f;
#pragma unroll 2
        for (int j = 0; j < d; j++) {
            float4 rec = g_pack[start + j];
            int i1 = __float_as_int(rec.y);
            int i2 = __float_as_int(rec.z);
            float2 h1 = *reinterpret_cast<const float2*>(&g_H1[i1 * HID + 2 * lane]);
            float2 h2 = *reinterpret_cast<const float2*>(&g_H2[i2 * HID + 2 * lane]);
            sumex += rec.x;
            acc.x += rec.x * (h1.x + h2.x);
            acc.y += rec.x * (h1.y + h2.y);
        }
        float2 h0 = *reinterpret_cast<const float2*>(&g_H0[gw * HID + 2 * lane]);
        float inv = 1.0f / sumex;
        o.x = (h0.x + acc.x * inv) * (1.0f / 3.0f) + bz.x;
        o.y = (h0.y + acc.y * inv) * (1.0f / 3.0f) + bz.y;
    }
    *reinterpret_cast<float2*>(&out[gw * HID + 2 * lane]) = o;
}

// ---------------- launch ----------------
extern "C" void kernel_launch(void* const* d_in, const int* in_sizes, int n_in,
                              void* d_out, int out_size) {
    const float* feats[3] = {0, 0, 0};
    const int* edges[3] = {0, 0, 0};
    const float *W_feat = 0, *b_feat = 0, *W_att = 0, *b_att = 0, *bias = 0;
    int nf = 0, ne = 0;
    for (int i = 0; i < n_in; i++) {
        int s = in_sizes[i];
        if (s == NN * KF) { if (nf < 3) feats[nf++] = (const float*)d_in[i]; }
        else if (s == NE) { if (ne < 3) edges[ne++] = (const int*)d_in[i]; }
        else if (s == KF * HID) W_feat = (const float*)d_in[i];
        else if (s == 2 * HID) W_att = (const float*)d_in[i];
        else if (s == HID) { if (!b_feat) b_feat = (const float*)d_in[i]; else bias = (const float*)d_in[i]; }
        else if (s == 1) b_att = (const float*)d_in[i];
    }
    float* out = (float*)d_out;

    zero_kernel<<<(NN + 255) / 256, 256>>>();
    gemm_kernel<<<dim3((NN + 255) / 256, 3), 256>>>(feats[0], feats[1], feats[2],
                                                    W_feat, b_feat, W_att, b_att);
    hist_kernel<<<(NE / 4 + 255) / 256, 256>>>(edges[0]);
    scan1_kernel<<<(NN + 1023) / 1024, 1024>>>();
    scan2_kernel<<<1, 32>>>((NN + 1023) / 1024);
    scan3_kernel<<<(NN + 1023) / 1024, 1024>>>();
    edge_kernel<<<(NE / 4 + 255) / 256, 256>>>(edges[0], edges[1], edges[2]);
    agg_kernel<<<(NN * 32 + 255) / 256, 256>>>(bias, out);
}

// round 5
// speedup vs baseline: 2.2054x; 1.2550x over previous
#include <cuda_runtime.h>
#include <cstdint>

#define NN 100000
#define NE 1000000
#define KF 128
#define HID 64

// ---------------- scratch ----------------
__device__ float g_H0[NN * HID];
__device__ float g_H1[NN * HID];
__device__ float g_H2[NN * HID];
__device__ float g_s00[NN];          // H0.Wa_top + H0.Wa_bot/3 + b_att
__device__ float g_sb1[NN];          // H1.Wa_bot/3
__device__ float g_sb2[NN];          // H2.Wa_bot/3
__device__ int   g_deg[NN];
__device__ int   g_offs[NN];         // exclusive offsets; end-offsets after edge pass
__device__ int   g_part[128];
__device__ float4 g_pack[NE];        // {ex, i1, i2, pad}

// ---------------- helpers ----------------
__device__ __forceinline__ uint32_t tf32_rna(float x) {
    uint32_t u;
    asm("cvt.rna.tf32.f32 %0, %1;" : "=r"(u) : "f"(x));
    return u;
}

// ---------------- kernel 0: zero degree ----------------
__global__ void zero_kernel() {
    int i = blockIdx.x * blockDim.x + threadIdx.x;
    if (i < NN) g_deg[i] = 0;
}

// ---------------- kernel 1: tf32 mma.sync GEMM (warp-level HMMA), fused epilogue ----
// Block: 256 threads = 8 warps; 128 rows x 64 cols per block; K=128.
// Per warp: 16 rows. mma m16n8k8, 8 n-tiles x 16 k-chunks = 128 MMAs/warp.
__global__ void __launch_bounds__(256) gemm_mma_kernel(
    const float* __restrict__ f0, const float* __restrict__ f1,
    const float* __restrict__ f2, const float* __restrict__ W,
    const float* __restrict__ b, const float* __restrict__ Wa,
    const float* __restrict__ b_att)
{
    __shared__ uint32_t Ws[KF][68];   // tf32 bits of W[k][n], padded: bank = (4k+n)&31, conflict-free

    int fk = blockIdx.y;
    const float* feat = (fk == 0) ? f0 : ((fk == 1) ? f1 : f2);
    float* H = (fk == 0) ? g_H0 : ((fk == 1) ? g_H1 : g_H2);
    int row0 = blockIdx.x * 128;
    int tid = threadIdx.x;
    int wid = tid >> 5, lane = tid & 31;

    // stage W (tf32-rounded), coalesced
#pragma unroll
    for (int i = 0; i < 32; i++) {
        int idx = tid + i * 256;             // 0..8191
        Ws[idx >> 6][idx & 63] = tf32_rna(W[idx]);
    }
    __syncthreads();

    int qk = lane & 3;                       // k-in-group / col-pair selector
    int qr = lane >> 2;                      // row / n selector
    int r  = row0 + wid * 16 + qr;           // rows m0..m0+7
    int r2 = r + 8;                          // rows m0+8..m0+15
    const float* pr  = feat + (size_t)((r  < NN) ? r  : NN - 1) * KF;
    const float* pr2 = feat + (size_t)((r2 < NN) ? r2 : NN - 1) * KF;

    float acc[8][4];
#pragma unroll
    for (int nt = 0; nt < 8; nt++)
#pragma unroll
        for (int j = 0; j < 4; j++) acc[nt][j] = 0.f;

#pragma unroll
    for (int kc = 0; kc < 16; kc++) {
        int k0 = kc * 8;
        uint32_t a0 = tf32_rna(pr [k0 + qk]);
        uint32_t a1 = tf32_rna(pr2[k0 + qk]);
        uint32_t a2 = tf32_rna(pr [k0 + qk + 4]);
        uint32_t a3 = tf32_rna(pr2[k0 + qk + 4]);
#pragma unroll
        for (int nt = 0; nt < 8; nt++) {
            uint32_t b0 = Ws[k0 + qk][nt * 8 + qr];
            uint32_t b1 = Ws[k0 + qk + 4][nt * 8 + qr];
            asm volatile(
                "mma.sync.aligned.m16n8k8.row.col.f32.tf32.tf32.f32 "
                "{%0,%1,%2,%3}, {%4,%5,%6,%7}, {%8,%9}, {%0,%1,%2,%3};"
                : "+f"(acc[nt][0]), "+f"(acc[nt][1]), "+f"(acc[nt][2]), "+f"(acc[nt][3])
                : "r"(a0), "r"(a1), "r"(a2), "r"(a3), "r"(b0), "r"(b1));
        }
    }

    // epilogue: bias add, store H, fused attention-scalar projections
    float ba = (fk == 0) ? __ldg(b_att) : 0.f;
    float pa = 0.f, pb = 0.f, pa2 = 0.f, pb2 = 0.f;
#pragma unroll
    for (int nt = 0; nt < 8; nt++) {
        int c = nt * 8 + 2 * qk;
        float2 bb = *reinterpret_cast<const float2*>(b + c);
        float2 wt = *reinterpret_cast<const float2*>(Wa + c);
        float2 wb = *reinterpret_cast<const float2*>(Wa + 64 + c);
        float o0 = acc[nt][0] + bb.x, o1 = acc[nt][1] + bb.y;
        float o2 = acc[nt][2] + bb.x, o3 = acc[nt][3] + bb.y;
        if (r < NN)
            *reinterpret_cast<float2*>(H + (size_t)r * HID + c) = make_float2(o0, o1);
        if (r2 < NN)
            *reinterpret_cast<float2*>(H + (size_t)r2 * HID + c) = make_float2(o2, o3);
        pa  += o0 * wt.x + o1 * wt.y;  pb  += o0 * wb.x + o1 * wb.y;
        pa2 += o2 * wt.x + o3 * wt.y;  pb2 += o2 * wb.x + o3 * wb.y;
    }
    // reduce over the 4 lanes sharing a row (lane&3)
#pragma unroll
    for (int off = 1; off <= 2; off <<= 1) {
        pa  += __shfl_xor_sync(0xffffffffu, pa,  off);
        pb  += __shfl_xor_sync(0xffffffffu, pb,  off);
        pa2 += __shfl_xor_sync(0xffffffffu, pa2, off);
        pb2 += __shfl_xor_sync(0xffffffffu, pb2, off);
    }
    if (qk == 0) {
        if (r < NN) {
            if (fk == 0)      g_s00[r] = pa + pb * (1.0f / 3.0f) + ba;
            else if (fk == 1) g_sb1[r] = pb * (1.0f / 3.0f);
            else              g_sb2[r] = pb * (1.0f / 3.0f);
        }
        if (r2 < NN) {
            if (fk == 0)      g_s00[r2] = pa2 + pb2 * (1.0f / 3.0f) + ba;
            else if (fk == 1) g_sb1[r2] = pb2 * (1.0f / 3.0f);
            else              g_sb2[r2] = pb2 * (1.0f / 3.0f);
        }
    }
}

// ---------------- kernel 2: degree histogram ----------------
__global__ void hist_kernel(const int* __restrict__ e0) {
    int i = blockIdx.x * blockDim.x + threadIdx.x;
    if (i < NE / 4) {
        int4 v = reinterpret_cast<const int4*>(e0)[i];
        atomicAdd(&g_deg[v.x], 1);
        atomicAdd(&g_deg[v.y], 1);
        atomicAdd(&g_deg[v.z], 1);
        atomicAdd(&g_deg[v.w], 1);
    }
}

// ---------------- kernels 3: exclusive scan ----------------
__global__ void scan1_kernel() {
    __shared__ int s[1024];
    int i = blockIdx.x * 1024 + threadIdx.x;
    int v = (i < NN) ? g_deg[i] : 0;
    s[threadIdx.x] = v;
    __syncthreads();
    for (int off = 1; off < 1024; off <<= 1) {
        int t = (threadIdx.x >= (unsigned)off) ? s[threadIdx.x - off] : 0;
        __syncthreads();
        s[threadIdx.x] += t;
        __syncthreads();
    }
    if (i < NN) g_offs[i] = s[threadIdx.x] - v;
    if (threadIdx.x == 1023) g_part[blockIdx.x] = s[1023];
}
__global__ void scan2_kernel(int nb) {
    __shared__ int s[128];
    int v = (threadIdx.x < (unsigned)nb) ? g_part[threadIdx.x] : 0;
    s[threadIdx.x] = v;
    __syncthreads();
    for (int off = 1; off < 128; off <<= 1) {
        int t = (threadIdx.x >= (unsigned)off) ? s[threadIdx.x - off] : 0;
        __syncthreads();
        s[threadIdx.x] += t;
        __syncthreads();
    }
    if (threadIdx.x < (unsigned)nb) g_part[threadIdx.x] = s[threadIdx.x] - v;
}
__global__ void scan3_kernel() {
    int i = blockIdx.x * 1024 + threadIdx.x;
    if (i < NN) g_offs[i] += g_part[blockIdx.x];
}

// ---------------- kernel 4: edge pass (offs doubles as cursor) ----------------
__global__ void edge_kernel(const int* __restrict__ e0, const int* __restrict__ e1,
                            const int* __restrict__ e2) {
    int i = blockIdx.x * blockDim.x + threadIdx.x;
    if (i >= NE / 4) return;
    int4 a = reinterpret_cast<const int4*>(e0)[i];
    int4 b = reinterpret_cast<const int4*>(e1)[i];
    int4 c = reinterpret_cast<const int4*>(e2)[i];
#pragma unroll
    for (int q = 0; q < 4; q++) {
        int n  = (q == 0) ? a.x : (q == 1) ? a.y : (q == 2) ? a.z : a.w;
        int i1 = (q == 0) ? b.x : (q == 1) ? b.y : (q == 2) ? b.z : b.w;
        int i2 = (q == 0) ? c.x : (q == 1) ? c.y : (q == 2) ? c.z : c.w;
        float sc = tanhf(g_s00[n] + g_sb1[i1] + g_sb2[i2]);
        float ex = __expf(sc);   // sc in [-1,1]: max-shift provably unnecessary
        int p = atomicAdd(&g_offs[n], 1);
        g_pack[p] = make_float4(ex, __int_as_float(i1), __int_as_float(i2), 0.f);
    }
}

// ---------------- kernel 5: per-node normalize + aggregate ----------------
__global__ __launch_bounds__(256) void agg_kernel(const float* __restrict__ bias,
                                                  float* __restrict__ out) {
    int gw = (blockIdx.x * 256 + threadIdx.x) >> 5;
    int lane = threadIdx.x & 31;
    if (gw >= NN) return;
    int d = g_deg[gw];
    int start = g_offs[gw] - d;   // offs is end-offset after edge pass
    float2 bz = *reinterpret_cast<const float2*>(&bias[2 * lane]);
    float2 o;
    if (d == 0) {
        o = bz;
    } else {
        float2 acc = make_float2(0.f, 0.f);
        float sumex = 0.f;
#pragma unroll 4
        for (int j = 0; j < d; j++) {
            float4 rec = g_pack[start + j];
            int i1 = __float_as_int(rec.y);
            int i2 = __float_as_int(rec.z);
            float2 h1 = *reinterpret_cast<const float2*>(&g_H1[i1 * HID + 2 * lane]);
            float2 h2 = *reinterpret_cast<const float2*>(&g_H2[i2 * HID + 2 * lane]);
            sumex += rec.x;
            acc.x += rec.x * (h1.x + h2.x);
            acc.y += rec.x * (h1.y + h2.y);
        }
        float2 h0 = *reinterpret_cast<const float2*>(&g_H0[gw * HID + 2 * lane]);
        float inv = 1.0f / sumex;
        o.x = (h0.x + acc.x * inv) * (1.0f / 3.0f) + bz.x;
        o.y = (h0.y + acc.y * inv) * (1.0f / 3.0f) + bz.y;
    }
    *reinterpret_cast<float2*>(&out[gw * HID + 2 * lane]) = o;
}

// ---------------- launch ----------------
extern "C" void kernel_launch(void* const* d_in, const int* in_sizes, int n_in,
                              void* d_out, int out_size) {
    const float* feats[3] = {0, 0, 0};
    const int* edges[3] = {0, 0, 0};
    const float *W_feat = 0, *b_feat = 0, *W_att = 0, *b_att = 0, *bias = 0;
    int nf = 0, ne = 0;
    for (int i = 0; i < n_in; i++) {
        int s = in_sizes[i];
        if (s == NN * KF) { if (nf < 3) feats[nf++] = (const float*)d_in[i]; }
        else if (s == NE) { if (ne < 3) edges[ne++] = (const int*)d_in[i]; }
        else if (s == KF * HID) W_feat = (const float*)d_in[i];
        else if (s == 2 * HID) W_att = (const float*)d_in[i];
        else if (s == HID) { if (!b_feat) b_feat = (const float*)d_in[i]; else bias = (const float*)d_in[i]; }
        else if (s == 1) b_att = (const float*)d_in[i];
    }
    float* out = (float*)d_out;

    zero_kernel<<<(NN + 255) / 256, 256>>>();
    gemm_mma_kernel<<<dim3((NN + 127) / 128, 3), 256>>>(
        feats[0], feats[1], feats[2], W_feat, b_feat, W_att, b_att);
    hist_kernel<<<(NE / 4 + 255) / 256, 256>>>(edges[0]);
    scan1_kernel<<<(NN + 1023) / 1024, 1024>>>();
    scan2_kernel<<<1, 128>>>((NN + 1023) / 1024);
    scan3_kernel<<<(NN + 1023) / 1024, 1024>>>();
    edge_kernel<<<(NE / 4 + 255) / 256, 256>>>(edges[0], edges[1], edges[2]);
    agg_kernel<<<(NN * 32 + 255) / 256, 256>>>(bias, out);
}